// round 1
// baseline (speedup 1.0000x reference)
#include <cuda_runtime.h>
#include <cstdint>

#define B_ 2
#define T_ 2048
#define S_ 2048
#define E_ 1024
#define H_ 16
#define D_ 64
#define M_ (B_*T_)

// Scratch (device globals; no allocation allowed)
__device__ float g_q[B_*H_*T_*D_];
__device__ float g_k[B_*H_*S_*D_];
__device__ float g_v[B_*H_*S_*D_];
__device__ float g_attn[M_*E_];

// ---------------------------------------------------------------------------
// GEMM: out[m][n] = sum_k A[m][k] * W[n][k] + bias[n]
// M=4096, N=1024, K=1024.  64x64 tile, 256 threads, 4x4 per thread.
// headMajor=1: write out[((b*H+h)*T + t)*D + d] with m=(b,t), n=(h,d)
// ---------------------------------------------------------------------------
__global__ void __launch_bounds__(256) gemm_kernel(
    const float* __restrict__ A, const float* __restrict__ W,
    const float* __restrict__ bias, float* __restrict__ out, int headMajor)
{
    __shared__ float As[16][68];
    __shared__ float Ws[16][68];
    const int tid = threadIdx.x;
    const int tx = tid & 15, ty = tid >> 4;
    const int m0 = blockIdx.y * 64, n0 = blockIdx.x * 64;
    const int lr = tid >> 2;
    const int lk = (tid & 3) * 4;

    float acc[4][4];
#pragma unroll
    for (int i = 0; i < 4; i++)
#pragma unroll
        for (int j = 0; j < 4; j++) acc[i][j] = 0.f;

    const float* Arow = A + (size_t)(m0 + lr) * E_ + lk;
    const float* Wrow = W + (size_t)(n0 + lr) * E_ + lk;

    for (int kt = 0; kt < E_; kt += 16) {
        float4 a = *(const float4*)(Arow + kt);
        float4 w = *(const float4*)(Wrow + kt);
        As[lk + 0][lr] = a.x; As[lk + 1][lr] = a.y;
        As[lk + 2][lr] = a.z; As[lk + 3][lr] = a.w;
        Ws[lk + 0][lr] = w.x; Ws[lk + 1][lr] = w.y;
        Ws[lk + 2][lr] = w.z; Ws[lk + 3][lr] = w.w;
        __syncthreads();
#pragma unroll
        for (int k = 0; k < 16; k++) {
            float4 av = *(const float4*)&As[k][ty * 4];
            float4 wv = *(const float4*)&Ws[k][tx * 4];
            float am[4] = {av.x, av.y, av.z, av.w};
            float wm[4] = {wv.x, wv.y, wv.z, wv.w};
#pragma unroll
            for (int i = 0; i < 4; i++)
#pragma unroll
                for (int j = 0; j < 4; j++)
                    acc[i][j] += am[i] * wm[j];
        }
        __syncthreads();
    }

#pragma unroll
    for (int i = 0; i < 4; i++) {
        const int m = m0 + ty * 4 + i;
#pragma unroll
        for (int j = 0; j < 4; j++) {
            const int n = n0 + tx * 4 + j;
            const float vout = acc[i][j] + bias[n];
            if (headMajor) {
                const int b = m >> 11, t = m & 2047;
                const int h = n >> 6,  d = n & 63;
                out[(size_t)((b * H_ + h) * T_ + t) * D_ + d] = vout;
            } else {
                out[(size_t)m * E_ + n] = vout;
            }
        }
    }
}

// ---------------------------------------------------------------------------
// Flash attention with additive biases.
// Grid (T/64, H, B), 256 threads. Each CTA: 64 query rows of one (b,h).
// thread (r = tid/4, g = tid%4): owns row r, cols c in [g*16, g*16+16) for
// scores, and d in [g*16, g*16+16) for the output accumulator.
// ---------------------------------------------------------------------------
#define ATTN_SMEM_FLOATS (64*65 + 64*64 + 64*64 + 64*68 + 64)
#define ATTN_SMEM_BYTES  (ATTN_SMEM_FLOATS * 4)

__global__ void __launch_bounds__(256) attn_kernel(
    const float* __restrict__ spatial, const float* __restrict__ dirb,
    const float* __restrict__ amask, const unsigned char* __restrict__ pmask,
    float* __restrict__ outp)
{
    extern __shared__ float sm[];
    float* Qs = sm;               // [64][65]
    float* Ks = Qs + 64 * 65;     // [64][64], transposed: Ks[k*64 + c]
    float* Vs = Ks + 64 * 64;     // [64][64]: Vs[c*64 + d]
    float* Ss = Vs + 64 * 64;     // [64][68]
    float* Ms = Ss + 64 * 68;     // [64] additive pad mask

    const int tid = threadIdx.x;
    const int t0 = blockIdx.x * 64;
    const int h  = blockIdx.y;
    const int b  = blockIdx.z;
    const int r  = tid >> 2;
    const int g  = tid & 3;

    const float* qbase = g_q + (size_t)((b * H_ + h) * T_ + t0) * D_;
    const float* kbase = g_k + (size_t)(b * H_ + h) * S_ * D_;
    const float* vbase = g_v + (size_t)(b * H_ + h) * S_ * D_;

    // Load Q tile: thread loads 16 floats of row (tid/4)
    {
        const int rl = tid >> 2;
        const int ko = (tid & 3) * 16;
        const float* src = qbase + rl * D_ + ko;
#pragma unroll
        for (int jj = 0; jj < 4; jj++) {
            float4 qv = *(const float4*)(src + jj * 4);
            Qs[rl * 65 + ko + jj * 4 + 0] = qv.x;
            Qs[rl * 65 + ko + jj * 4 + 1] = qv.y;
            Qs[rl * 65 + ko + jj * 4 + 2] = qv.z;
            Qs[rl * 65 + ko + jj * 4 + 3] = qv.w;
        }
    }

    float m_i = -1e30f, l_i = 0.f;
    float acc[16];
#pragma unroll
    for (int i = 0; i < 16; i++) acc[i] = 0.f;

    const float scale = 0.125f;  // 1/sqrt(64)

    for (int s0 = 0; s0 < S_; s0 += 64) {
        // K tile, transposed to Ks[k][c]
        {
            const int c  = tid & 63;
            const int kq = tid >> 6;   // 0..3
            const float* src = kbase + (size_t)(s0 + c) * D_;
#pragma unroll
            for (int it = 0; it < 4; it++) {
                const int k4 = (kq + it * 4) * 4;
                float4 kv = *(const float4*)(src + k4);
                Ks[(k4 + 0) * 64 + c] = kv.x;
                Ks[(k4 + 1) * 64 + c] = kv.y;
                Ks[(k4 + 2) * 64 + c] = kv.z;
                Ks[(k4 + 3) * 64 + c] = kv.w;
            }
        }
        // V tile
        {
            const int d4 = (tid & 15) * 4;
            const int cv = tid >> 4;   // 0..15
#pragma unroll
            for (int it = 0; it < 4; it++) {
                const int c = cv + it * 16;
                *(float4*)&Vs[c * 64 + d4] =
                    *(const float4*)(vbase + (size_t)(s0 + c) * D_ + d4);
            }
        }
        if (tid < 64)
            Ms[tid] = pmask[b * S_ + s0 + tid] ? -1e30f : 0.f;
        __syncthreads();

        // ---- scores: sc[c'] = dot(Q[r], K[c]) for 16 consecutive c ----
        float sc[16];
#pragma unroll
        for (int i = 0; i < 16; i++) sc[i] = 0.f;
#pragma unroll 4
        for (int k = 0; k < 64; k++) {
            const float qv = Qs[r * 65 + k];
            const float* kr = &Ks[k * 64 + g * 16];
            float4 k0 = *(const float4*)(kr);
            float4 k1 = *(const float4*)(kr + 4);
            float4 k2 = *(const float4*)(kr + 8);
            float4 k3 = *(const float4*)(kr + 12);
            sc[0]  += qv * k0.x; sc[1]  += qv * k0.y; sc[2]  += qv * k0.z; sc[3]  += qv * k0.w;
            sc[4]  += qv * k1.x; sc[5]  += qv * k1.y; sc[6]  += qv * k1.z; sc[7]  += qv * k1.w;
            sc[8]  += qv * k2.x; sc[9]  += qv * k2.y; sc[10] += qv * k2.z; sc[11] += qv * k2.w;
            sc[12] += qv * k3.x; sc[13] += qv * k3.y; sc[14] += qv * k3.z; sc[15] += qv * k3.w;
        }

        // ---- biases + masks (each element read exactly once globally) ----
        const size_t brow = ((size_t)(b * H_ + h) * T_ + (t0 + r)) * S_ + s0 + g * 16;
        const float* sprow = spatial + brow;
        const float* drow  = dirb + brow;
        const float* arow  = amask + (size_t)(t0 + r) * S_ + s0 + g * 16;
#pragma unroll
        for (int ii = 0; ii < 4; ii++) {
            float4 sp = *(const float4*)(sprow + ii * 4);
            float4 dv = *(const float4*)(drow + ii * 4);
            float4 av = *(const float4*)(arow + ii * 4);
            sc[ii*4+0] = sc[ii*4+0] * scale + av.x + Ms[g*16 + ii*4 + 0] + sp.x + dv.x;
            sc[ii*4+1] = sc[ii*4+1] * scale + av.y + Ms[g*16 + ii*4 + 1] + sp.y + dv.y;
            sc[ii*4+2] = sc[ii*4+2] * scale + av.z + Ms[g*16 + ii*4 + 2] + sp.z + dv.z;
            sc[ii*4+3] = sc[ii*4+3] * scale + av.w + Ms[g*16 + ii*4 + 3] + sp.w + dv.w;
        }

        // ---- online softmax (row shared by 4 lanes of a quad) ----
        float mloc = m_i;
#pragma unroll
        for (int i = 0; i < 16; i++) mloc = fmaxf(mloc, sc[i]);
        mloc = fmaxf(mloc, __shfl_xor_sync(0xFFFFFFFFu, mloc, 1));
        mloc = fmaxf(mloc, __shfl_xor_sync(0xFFFFFFFFu, mloc, 2));

        const float alpha = __expf(m_i - mloc);
        float lsum = 0.f;
#pragma unroll
        for (int i = 0; i < 16; i++) {
            const float p = __expf(sc[i] - mloc);
            lsum += p;
            Ss[r * 68 + g * 16 + i] = p;
        }
        lsum += __shfl_xor_sync(0xFFFFFFFFu, lsum, 1);
        lsum += __shfl_xor_sync(0xFFFFFFFFu, lsum, 2);
        l_i = l_i * alpha + lsum;
        m_i = mloc;
#pragma unroll
        for (int i = 0; i < 16; i++) acc[i] *= alpha;
        __syncthreads();

        // ---- PV: acc[d'] += sum_c P[r][c] * V[c][d] ----
#pragma unroll 4
        for (int c = 0; c < 64; c++) {
            const float p = Ss[r * 68 + c];
            const float* vr = &Vs[c * 64 + g * 16];
            float4 v0 = *(const float4*)(vr);
            float4 v1 = *(const float4*)(vr + 4);
            float4 v2 = *(const float4*)(vr + 8);
            float4 v3 = *(const float4*)(vr + 12);
            acc[0]  += p * v0.x; acc[1]  += p * v0.y; acc[2]  += p * v0.z; acc[3]  += p * v0.w;
            acc[4]  += p * v1.x; acc[5]  += p * v1.y; acc[6]  += p * v1.z; acc[7]  += p * v1.w;
            acc[8]  += p * v2.x; acc[9]  += p * v2.y; acc[10] += p * v2.z; acc[11] += p * v2.w;
            acc[12] += p * v3.x; acc[13] += p * v3.y; acc[14] += p * v3.z; acc[15] += p * v3.w;
        }
        __syncthreads();
    }

    const float inv = 1.f / l_i;
    float* orow = outp + (size_t)(b * T_ + t0 + r) * E_ + h * D_ + g * 16;
#pragma unroll
    for (int ii = 0; ii < 4; ii++) {
        float4 o;
        o.x = acc[ii*4+0] * inv;
        o.y = acc[ii*4+1] * inv;
        o.z = acc[ii*4+2] * inv;
        o.w = acc[ii*4+3] * inv;
        *(float4*)(orow + ii * 4) = o;
    }
}

// ---------------------------------------------------------------------------
extern "C" void kernel_launch(void* const* d_in, const int* in_sizes, int n_in,
                              void* d_out, int out_size)
{
    const float* query = (const float*)d_in[0];
    const float* key   = (const float*)d_in[1];
    const float* value = (const float*)d_in[2];
    const float* spatial = (const float*)d_in[3];
    const float* dirb    = (const float*)d_in[4];
    const unsigned char* pmask = (const unsigned char*)d_in[5];
    const float* amask = (const float*)d_in[6];
    const float* Wq = (const float*)d_in[7];
    const float* bq = (const float*)d_in[8];
    const float* Wk = (const float*)d_in[9];
    const float* bk = (const float*)d_in[10];
    const float* Wv = (const float*)d_in[11];
    const float* bv = (const float*)d_in[12];
    const float* Wo = (const float*)d_in[13];
    const float* bo = (const float*)d_in[14];
    float* out = (float*)d_out;

    float *qp, *kp, *vp, *ap;
    cudaGetSymbolAddress((void**)&qp, g_q);
    cudaGetSymbolAddress((void**)&kp, g_k);
    cudaGetSymbolAddress((void**)&vp, g_v);
    cudaGetSymbolAddress((void**)&ap, g_attn);

    cudaFuncSetAttribute(attn_kernel,
                         cudaFuncAttributeMaxDynamicSharedMemorySize,
                         ATTN_SMEM_BYTES);

    const dim3 gb(E_ / 64, M_ / 64);   // (16, 64)
    gemm_kernel<<<gb, 256>>>(query, Wq, bq, qp, 1);
    gemm_kernel<<<gb, 256>>>(key,   Wk, bk, kp, 1);
    gemm_kernel<<<gb, 256>>>(value, Wv, bv, vp, 1);

    attn_kernel<<<dim3(T_ / 64, H_, B_), 256, ATTN_SMEM_BYTES>>>(
        spatial, dirb, amask, pmask, ap);

    gemm_kernel<<<gb, 256>>>(ap, Wo, bo, out, 0);
}